// round 17
// baseline (speedup 1.0000x reference)
#include <cuda_runtime.h>
#include <cuda_fp16.h>
#include <math.h>
#include <stdint.h>

// ---------------- problem constants ----------------
#define BB 32
#define TT 512
#define DD 512
#define LL 6
#define HH 8
#define HD 64
#define FF 2048      // 4*D
#define EH 4
#define EHD 128
#define MM 100000u
#define OVL 64
#define NTOK (BB*TT)   // 16384

// ---------------- scratch ----------------
__device__ float g_x[NTOK*DD];
__device__ float g_ctx[BB*DD];
__device__ float g_logits[NTOK*EH];
__device__ float g_wv[BB*DD];
__device__ float g_u[BB*EH];
__device__ float2 g_ropetab[TT*32];
// fp16 activations
__device__ __half g_qkv[(size_t)NTOK*3*DD];
__device__ __half g_nx[NTOK*DD];
__device__ __half g_at[NTOK*DD];
__device__ __half g_ff[(size_t)NTOK*FF];
// transposed fp16 weights: [N][K]
__device__ __half g_wqkvo[(size_t)LL*4*DD*DD];
__device__ __half g_w1[(size_t)LL*2*FF*DD];
__device__ __half g_w2[(size_t)LL*DD*FF];

// ---------------- PTX helpers ----------------
__device__ __forceinline__ uint32_t smem_to_u32(const void* p) {
    uint32_t a;
    asm("{ .reg .u64 t; cvta.to.shared.u64 t, %1; cvt.u32.u64 %0, t; }" : "=r"(a) : "l"(p));
    return a;
}
__device__ __forceinline__ void cp16(uint32_t dst, const void* src) {
    asm volatile("cp.async.cg.shared.global [%0], [%1], 16;" :: "r"(dst), "l"(src));
}
#define CP_COMMIT() asm volatile("cp.async.commit_group;" ::: "memory")
#define CP_WAIT2()  asm volatile("cp.async.wait_group 2;" ::: "memory")

#define LDSM4(r, addr) \
    asm volatile("ldmatrix.sync.aligned.m8n8.x4.shared.b16 {%0,%1,%2,%3}, [%4];" \
        : "=r"((r)[0]), "=r"((r)[1]), "=r"((r)[2]), "=r"((r)[3]) : "r"(addr))

#define HMMA(c, a, b0, b1) \
    asm volatile("mma.sync.aligned.m16n8k16.row.col.f32.f16.f16.f32 " \
        "{%0,%1,%2,%3}, {%4,%5,%6,%7}, {%8,%9}, {%0,%1,%2,%3};" \
        : "+f"((c)[0]), "+f"((c)[1]), "+f"((c)[2]), "+f"((c)[3]) \
        : "r"((a)[0]), "r"((a)[1]), "r"((a)[2]), "r"((a)[3]), "r"(b0), "r"(b1))

__device__ __forceinline__ uint32_t f22u(float a, float b) {
    __half2 h = __floats2half2_rn(a, b);
    return *(uint32_t*)&h;
}

// ---------------- reduction helpers ----------------
__device__ __forceinline__ float warpReduceSum(float v) {
    #pragma unroll
    for (int o = 16; o; o >>= 1) v += __shfl_xor_sync(0xffffffffu, v, o);
    return v;
}
__device__ __forceinline__ float warpReduceMax(float v) {
    #pragma unroll
    for (int o = 16; o; o >>= 1) v = fmaxf(v, __shfl_xor_sync(0xffffffffu, v, o));
    return v;
}
__device__ __forceinline__ float blockReduceSum128(float v) {
    __shared__ float sm[4];
    __syncthreads();
    v = warpReduceSum(v);
    if ((threadIdx.x & 31) == 0) sm[threadIdx.x >> 5] = v;
    __syncthreads();
    return sm[0] + sm[1] + sm[2] + sm[3];
}
__device__ __forceinline__ float blockReduceSum512(float v) {
    __shared__ float sm[16];
    __syncthreads();
    v = warpReduceSum(v);
    if ((threadIdx.x & 31) == 0) sm[threadIdx.x >> 5] = v;
    __syncthreads();
    float r = 0.f;
    #pragma unroll
    for (int i = 0; i < 16; i++) r += sm[i];
    return r;
}
__device__ __forceinline__ float blockReduceMax512(float v) {
    __shared__ float sm[16];
    __syncthreads();
    v = warpReduceMax(v);
    if ((threadIdx.x & 31) == 0) sm[threadIdx.x >> 5] = v;
    __syncthreads();
    float r = -1e30f;
    #pragma unroll
    for (int i = 0; i < 16; i++) r = fmaxf(r, sm[i]);
    return r;
}
__device__ __forceinline__ float groupReduceSum128of512(float v) {
    __shared__ float sm[16];
    __syncthreads();
    v = warpReduceSum(v);
    if ((threadIdx.x & 31) == 0) sm[threadIdx.x >> 5] = v;
    __syncthreads();
    int g4 = (threadIdx.x >> 7) << 2;
    return sm[g4] + sm[g4+1] + sm[g4+2] + sm[g4+3];
}

// ---------------- rope cos/sin table ----------------
__global__ void rope_table_kernel(float2* __restrict__ tab) {
    int t = blockIdx.x, j = threadIdx.x;   // 512 x 32
    const float c = 9.210340371976184f / 64.f;
    float inv = __expf(-(float)(2*j) * c);
    float s, co;
    __sincosf((float)t * inv, &s, &co);
    tab[t*32 + j] = make_float2(co, s);
}

// ---------------- 4-source transpose to fp16 (Wq/Wk/Wv/Wo stacked) ----------------
__global__ void tsplit4_kernel(const float* __restrict__ s0, const float* __restrict__ s1,
                               const float* __restrict__ s2, const float* __restrict__ s3,
                               __half* __restrict__ dst) {
    __shared__ float t[32][33];
    int z = blockIdx.z;
    int l = z >> 2, sel = z & 3;
    const float* S = (sel == 0 ? s0 : sel == 1 ? s1 : sel == 2 ? s2 : s3) + (size_t)l*DD*DD;
    __half* Hd = dst + (size_t)z*DD*DD;
    int n0 = blockIdx.x*32, k0 = blockIdx.y*32;
    int x = threadIdx.x, y = threadIdx.y;
    #pragma unroll
    for (int i = 0; i < 32; i += 8) t[y+i][x] = S[(size_t)(k0+y+i)*DD + n0+x];
    __syncthreads();
    #pragma unroll
    for (int i = 0; i < 32; i += 8)
        Hd[(size_t)(n0+y+i)*DD + k0+x] = __float2half_rn(t[x][y+i]);
}

// ---------------- generic transpose to fp16 ----------------
__global__ void tsplit_kernel(const float* __restrict__ src, int ldsrc, size_t srcStride,
                              __half* __restrict__ dst, size_t dstStride, int K) {
    __shared__ float t[32][33];
    int l = blockIdx.z;
    const float* S = src + (size_t)l*srcStride;
    __half* Hd = dst + (size_t)l*dstStride;
    int n0 = blockIdx.x*32, k0 = blockIdx.y*32;
    int x = threadIdx.x, y = threadIdx.y;
    #pragma unroll
    for (int i = 0; i < 32; i += 8) t[y+i][x] = S[(size_t)(k0+y+i)*ldsrc + n0+x];
    __syncthreads();
    #pragma unroll
    for (int i = 0; i < 32; i += 8)
        Hd[(size_t)(n0+y+i)*K + k0+x] = __float2half_rn(t[x][y+i]);
}

// ---------------- W1 transpose to fp16 ----------------
__global__ void tsplitW1_kernel(const float* __restrict__ W1, __half* __restrict__ dst) {
    __shared__ float t[32][33];
    int z = blockIdx.z;
    int l = z >> 1, half = z & 1;
    const float* S = W1 + (size_t)l*DD*2*FF + (size_t)half*FF;
    __half* Hd = dst + (size_t)l*2*FF*DD + (size_t)half*FF*DD;
    int n0 = blockIdx.x*32, k0 = blockIdx.y*32;
    int x = threadIdx.x, y = threadIdx.y;
    #pragma unroll
    for (int i = 0; i < 32; i += 8) t[y+i][x] = S[(size_t)(k0+y+i)*(2*FF) + n0+x];
    __syncthreads();
    #pragma unroll
    for (int i = 0; i < 32; i += 8)
        Hd[(size_t)(n0+y+i)*DD + k0+x] = __float2half_rn(t[x][y+i]);
}

// ---------------- fp16 HMMA GEMM (single pass, 4-stage cp.async) ----------------
// MODE 0: +bias3 (QKV select) + fused RoPE on Q/K cols, fp16 out ;
// MODE 1: +bias +res, fp32 out ; MODE 4: +res, fp32 out
#define TILE_B 10240
#define STAGE_B 20480
#define HSMEM (4*STAGE_B)

__device__ __forceinline__ void load_stage(uint32_t sb,
        const __half* A, const __half* B, int K, int kof, int tid) {
    #pragma unroll
    for (int i = 0; i < 2; i++) {
        int e = tid + i*256;
        int row = e >> 2, seg = e & 3;
        uint32_t off = (uint32_t)(row*80 + seg*16);
        size_t g = (size_t)row*K + kof + seg*8;
        cp16(sb + off,          A + g);
        cp16(sb + TILE_B + off, B + g);
    }
}

__device__ __forceinline__ float2 rot2(float2 v, float2 cs) {
    return make_float2(v.x*cs.x - v.y*cs.y, v.x*cs.y + v.y*cs.x);
}

template<int MODE>
__global__ void __launch_bounds__(256, 2)
hgemm(const __half* __restrict__ A, const __half* __restrict__ B,
      const float* __restrict__ bias, const float* __restrict__ bias2,
      const float* __restrict__ bias3,
      const float* __restrict__ Res, const float2* __restrict__ rope,
      float* __restrict__ C, __half* __restrict__ OutH,
      int M, int N, int K) {
    extern __shared__ char dsm[];
    uint32_t sb = smem_to_u32(dsm);
    int tid = threadIdx.x, lane = tid & 31, wid = tid >> 5;
    int m0 = blockIdx.x * 128, n0 = blockIdx.y * 128;
    int wm = (wid & 1) * 64, wn = (wid >> 1) * 32;
    const __half* Ab = A + (size_t)m0*K;
    const __half* Bb = B + (size_t)n0*K;
    int NC = K >> 5;

    load_stage(sb,             Ab, Bb, K, 0,  tid); CP_COMMIT();
    load_stage(sb + STAGE_B,   Ab, Bb, K, 32, tid); CP_COMMIT();
    load_stage(sb + 2*STAGE_B, Ab, Bb, K, 64, tid); CP_COMMIT();

    float acc[4][4][4];
    #pragma unroll
    for (int a = 0; a < 4; a++)
        #pragma unroll
        for (int b = 0; b < 4; b++)
            #pragma unroll
            for (int c = 0; c < 4; c++) acc[a][b][c] = 0.f;

    const int a_row = lane & 15;
    const int a_k   = (lane >> 4) * 8;
    const int b_row = (lane & 7) + ((lane >> 4) << 3);
    const int b_k   = ((lane >> 3) & 1) * 8;

    for (int i = 0; i < NC; i++) {
        CP_WAIT2();
        __syncthreads();
        if (i + 3 < NC)
            load_stage(sb + (uint32_t)((i+3) & 3)*STAGE_B, Ab, Bb, K, (i+3)*32, tid);
        CP_COMMIT();
        uint32_t st = sb + (uint32_t)(i & 3)*STAGE_B;
        #pragma unroll
        for (int kk = 0; kk < 32; kk += 16) {
            uint32_t a4[4][4], b2[2][4];
            #pragma unroll
            for (int mt = 0; mt < 4; mt++) {
                uint32_t ad = st + (uint32_t)((wm + mt*16 + a_row)*80 + (kk + a_k)*2);
                LDSM4(a4[mt], ad);
            }
            #pragma unroll
            for (int np = 0; np < 2; np++) {
                uint32_t bd = st + TILE_B + (uint32_t)((wn + np*16 + b_row)*80 + (kk + b_k)*2);
                LDSM4(b2[np], bd);
            }
            #pragma unroll
            for (int mt = 0; mt < 4; mt++)
                #pragma unroll
                for (int nt = 0; nt < 4; nt++)
                    HMMA(acc[mt][nt], a4[mt], b2[nt>>1][(nt&1)*2], b2[nt>>1][(nt&1)*2+1]);
        }
    }

    int gid = lane >> 2, ctg = lane & 3;
    #pragma unroll
    for (int mt = 0; mt < 4; mt++)
        #pragma unroll
        for (int nt = 0; nt < 4; nt++) {
            int r0 = m0 + wm + mt*16 + gid;
            int cc = n0 + wn + nt*8 + ctg*2;
            float2 v0 = make_float2(acc[mt][nt][0], acc[mt][nt][1]);
            float2 v1 = make_float2(acc[mt][nt][2], acc[mt][nt][3]);
            if (MODE == 0) {
                const float* bp = (cc < 512) ? (bias + cc)
                                : (cc < 1024) ? (bias2 + cc - 512) : (bias3 + cc - 1024);
                float2 bb = *(const float2*)bp;
                v0.x += bb.x; v0.y += bb.y; v1.x += bb.x; v1.y += bb.y;
                if (cc < 1024) {       // fused RoPE for Q and K columns
                    int j = (cc & 63) >> 1;
                    v0 = rot2(v0, rope[(r0 & 511)*32 + j]);
                    v1 = rot2(v1, rope[((r0 + 8) & 511)*32 + j]);
                }
                *(__half2*)(OutH + (size_t)r0*N + cc)     = __floats2half2_rn(v0.x, v0.y);
                *(__half2*)(OutH + (size_t)(r0+8)*N + cc) = __floats2half2_rn(v1.x, v1.y);
            } else {
                if (MODE == 1) {
                    float2 bb = *(const float2*)(bias + cc);
                    v0.x += bb.x; v0.y += bb.y; v1.x += bb.x; v1.y += bb.y;
                }
                float2 ra = *(const float2*)(Res + (size_t)r0*N + cc);
                float2 rb = *(const float2*)(Res + (size_t)(r0+8)*N + cc);
                v0.x += ra.x; v0.y += ra.y; v1.x += rb.x; v1.y += rb.y;
                *(float2*)(C + (size_t)r0*N + cc) = v0;
                *(float2*)(C + (size_t)(r0+8)*N + cc) = v1;
            }
        }
}

// ---------------- fused gate+value FFN GEMM ----------------
#define FT_BG 10240
#define FT_BV 15360

__device__ __forceinline__ void load_stage_ffn(uint32_t sb,
        const __half* A, const __half* Bg, const __half* Bv, int K, int kof, int tid) {
    #pragma unroll
    for (int i = 0; i < 2; i++) {
        int e = tid + i*256;
        int row = e >> 2, seg = e & 3;
        uint32_t off = (uint32_t)(row*80 + seg*16);
        cp16(sb + off, A + (size_t)row*K + kof + seg*8);
    }
    {
        int row = tid >> 2, seg = tid & 3;
        uint32_t off = (uint32_t)(row*80 + seg*16);
        size_t g = (size_t)row*K + kof + seg*8;
        cp16(sb + FT_BG + off, Bg + g);
        cp16(sb + FT_BV + off, Bv + g);
    }
}

__global__ void __launch_bounds__(256, 2)
hgemm_ffn(const __half* __restrict__ A, const __half* __restrict__ Bg,
          const __half* __restrict__ Bv, __half* __restrict__ Out,
          int M, int N, int K) {
    extern __shared__ char dsm[];
    uint32_t sb = smem_to_u32(dsm);
    int tid = threadIdx.x, lane = tid & 31, wid = tid >> 5;
    int m0 = blockIdx.x * 128, n0 = blockIdx.y * 64;
    int wm = (wid & 1) * 64, wn = (wid >> 1) * 16;
    const __half* Ab  = A  + (size_t)m0*K;
    const __half* Bgb = Bg + (size_t)n0*K;
    const __half* Bvb = Bv + (size_t)n0*K;
    int NC = K >> 5;

    load_stage_ffn(sb,             Ab, Bgb, Bvb, K, 0,  tid); CP_COMMIT();
    load_stage_ffn(sb + STAGE_B,   Ab, Bgb, Bvb, K, 32, tid); CP_COMMIT();
    load_stage_ffn(sb + 2*STAGE_B, Ab, Bgb, Bvb, K, 64, tid); CP_COMMIT();

    float ag[4][2][4], av[4][2][4];
    #pragma unroll
    for (int a = 0; a < 4; a++)
        #pragma unroll
        for (int b = 0; b < 2; b++)
            #pragma unroll
            for (int c = 0; c < 4; c++) { ag[a][b][c] = 0.f; av[a][b][c] = 0.f; }

    const int a_row = lane & 15;
    const int a_k   = (lane >> 4) * 8;
    const int b_row = (lane & 7) + ((lane >> 4) << 3);
    const int b_k   = ((lane >> 3) & 1) * 8;

    for (int i = 0; i < NC; i++) {
        CP_WAIT2();
        __syncthreads();
        if (i + 3 < NC)
            load_stage_ffn(sb + (uint32_t)((i+3) & 3)*STAGE_B, Ab, Bgb, Bvb, K, (i+3)*32, tid);
        CP_COMMIT();
        uint32_t st = sb + (uint32_t)(i & 3)*STAGE_B;
        #pragma unroll
        for (int kk = 0; kk < 32; kk += 16) {
            uint32_t a4[4][4], bg[4], bv2[4];
            #pragma unroll
            for (int mt = 0; mt < 4; mt++) {
                uint32_t ad = st + (uint32_t)((wm + mt*16 + a_row)*80 + (kk + a_k)*2);
                LDSM4(a4[mt], ad);
            }
            uint32_t brow = (uint32_t)((wn + b_row)*80 + (kk + b_k)*2);
            LDSM4(bg,  st + FT_BG + brow);
            LDSM4(bv2, st + FT_BV + brow);
            #pragma unroll
            for (int mt = 0; mt < 4; mt++) {
                HMMA(ag[mt][0], a4[mt], bg[0],  bg[1]);
                HMMA(ag[mt][1], a4[mt], bg[2],  bg[3]);
                HMMA(av[mt][0], a4[mt], bv2[0], bv2[1]);
                HMMA(av[mt][1], a4[mt], bv2[2], bv2[3]);
            }
        }
    }

    int gid = lane >> 2, ctg = lane & 3;
    #pragma unroll
    for (int mt = 0; mt < 4; mt++)
        #pragma unroll
        for (int nt = 0; nt < 2; nt++) {
            int r0 = m0 + wm + mt*16 + gid;
            int cc = n0 + wn + nt*8 + ctg*2;
            float g0 = ag[mt][nt][0], g1 = ag[mt][nt][1];
            float g2 = ag[mt][nt][2], g3 = ag[mt][nt][3];
            float s0 = g0/(1.f+__expf(-g0))*av[mt][nt][0];
            float s1 = g1/(1.f+__expf(-g1))*av[mt][nt][1];
            float s2 = g2/(1.f+__expf(-g2))*av[mt][nt][2];
            float s3 = g3/(1.f+__expf(-g3))*av[mt][nt][3];
            *(__half2*)(Out + (size_t)r0*N + cc)     = __floats2half2_rn(s0, s1);
            *(__half2*)(Out + (size_t)(r0+8)*N + cc) = __floats2half2_rn(s2, s3);
        }
}

// ---------------- context projection (256 blocks, 8-way k-slice) ----------------
__global__ void __launch_bounds__(512) ctx_kernel(
        const float* __restrict__ fast, const float* __restrict__ slow,
        const float* __restrict__ W, const float* __restrict__ bias,
        float* __restrict__ out) {
    int b = blockIdx.x;
    int dl = threadIdx.x & 63;
    int d = blockIdx.y*64 + dl;
    int ks = threadIdx.x >> 6;
    __shared__ float sm[8][64];
    const float* fb = fast + b*DD;
    const float* sb = slow + b*DD;
    float acc = 0.f;
    #pragma unroll 4
    for (int k = ks*128; k < ks*128 + 128; k++) {
        float a = (k < DD) ? fb[k] : sb[k - DD];
        acc += a * W[(size_t)k*DD + d];
    }
    sm[ks][dl] = acc;
    __syncthreads();
    if (ks == 0) {
        float r = bias[d];
        #pragma unroll
        for (int i = 0; i < 8; i++) r += sm[i][dl];
        out[b*DD + d] = r;
    }
}

// ---------------- embedding + context + engram + fused layer-0 rmsnorm ----------------
__global__ void embed_fused_kernel(const int* __restrict__ tokens, const int* __restrict__ prev,
                                   const float* __restrict__ embed, const float* __restrict__ ctxadd,
                                   const float* __restrict__ etab, const float* __restrict__ egate,
                                   const float* __restrict__ ln1,
                                   float* __restrict__ X, __half* __restrict__ H) {
    int row = blockIdx.x;
    int b = row >> 9, t = row & 511;
    __shared__ unsigned int sidx[EH];
    int tid = threadIdx.x;
    if (tid < EH) {
        unsigned int xseed = 131u + (unsigned)tid * 1009u;
        unsigned int hs = 0u;
        #pragma unroll
        for (int i = 0; i < 4; i++) {
            unsigned int p = xseed; xseed = xseed * 31u + 1u;
            int pos = t - i;
            unsigned int tok = (pos >= 0) ? (unsigned)tokens[b*TT + pos]
                                          : (unsigned)prev[b*OVL + OVL + pos];
            hs += tok * p;
        }
        sidx[tid] = hs % MM;
    }
    __syncthreads();
    int d0 = tid * 4;
    int eh = tid >> 5;
    int jj = d0 & 127;
    int tok = tokens[b*TT + t];
    float4 ev = *(const float4*)(embed + (size_t)tok*DD + d0);
    float4 cv = *(const float4*)(ctxadd + b*DD + d0);
    float4 rv = *(const float4*)(etab + ((size_t)sidx[eh]*EH + eh)*EHD + jj);
    float4 gv = *(const float4*)(egate + eh*EHD + jj);
    float4 o;
    o.x = ev.x + cv.x + rv.x * (1.f/(1.f+__expf(-gv.x)));
    o.y = ev.y + cv.y + rv.y * (1.f/(1.f+__expf(-gv.y)));
    o.z = ev.z + cv.z + rv.z * (1.f/(1.f+__expf(-gv.z)));
    o.w = ev.w + cv.w + rv.w * (1.f/(1.f+__expf(-gv.w)));
    *(float4*)(X + (size_t)row*DD + d0) = o;
    float ss = blockReduceSum128(o.x*o.x + o.y*o.y + o.z*o.z + o.w*o.w);
    float inv = rsqrtf(ss * (1.f/DD) + 1e-6f);
    float4 sc = ((const float4*)ln1)[tid];
    size_t off = (size_t)row*DD + d0;
    *(__half2*)(H + off)     = __floats2half2_rn(o.x*inv*sc.x, o.y*inv*sc.y);
    *(__half2*)(H + off + 2) = __floats2half2_rn(o.z*inv*sc.z, o.w*inv*sc.w);
}

// ---------------- RMSNorm -> fp16 plane (4 rows per 512-thread block) ----------------
__global__ void __launch_bounds__(512) rmsnorm_half_kernel(
        const float* __restrict__ X, const float* __restrict__ scale,
        __half* __restrict__ H) {
    int row = blockIdx.x*4 + (threadIdx.x >> 7);
    int t128 = threadIdx.x & 127;
    float4 v = ((const float4*)(X + (size_t)row*DD))[t128];
    float ss = groupReduceSum128of512(v.x*v.x + v.y*v.y + v.z*v.z + v.w*v.w);
    float inv = rsqrtf(ss * (1.f/DD) + 1e-6f);
    float4 sc = ((const float4*)scale)[t128];
    size_t off = (size_t)row*DD + t128*4;
    *(__half2*)(H + off)     = __floats2half2_rn(v.x*inv*sc.x, v.y*inv*sc.y);
    *(__half2*)(H + off + 2) = __floats2half2_rn(v.z*inv*sc.z, v.w*inv*sc.w);
}

// ---------------- final RMSNorm (fp32 out) + fused salience logits ----------------
__global__ void rmsnorm_logits_kernel(const float* __restrict__ X, const float* __restrict__ scale,
                                      const float* __restrict__ sal_W, const float* __restrict__ sal_b,
                                      const float* __restrict__ temp,
                                      float* __restrict__ Out, float* __restrict__ logits) {
    int row = blockIdx.x;
    float4 v = ((const float4*)(X + (size_t)row*DD))[threadIdx.x];
    float ss = blockReduceSum128(v.x*v.x + v.y*v.y + v.z*v.z + v.w*v.w);
    float inv = rsqrtf(ss * (1.f/DD) + 1e-6f);
    float4 sc = ((const float4*)scale)[threadIdx.x];
    float4 o;
    o.x = v.x*inv*sc.x; o.y = v.y*inv*sc.y; o.z = v.z*inv*sc.z; o.w = v.w*inv*sc.w;
    ((float4*)(Out + (size_t)row*DD))[threadIdx.x] = o;
    int d0 = threadIdx.x * 4;
    float4 w0 = *(const float4*)(sal_W + (d0+0)*EH);
    float4 w1 = *(const float4*)(sal_W + (d0+1)*EH);
    float4 w2 = *(const float4*)(sal_W + (d0+2)*EH);
    float4 w3 = *(const float4*)(sal_W + (d0+3)*EH);
    float a0 = o.x*w0.x + o.y*w1.x + o.z*w2.x + o.w*w3.x;
    float a1 = o.x*w0.y + o.y*w1.y + o.z*w2.y + o.w*w3.y;
    float a2 = o.x*w0.z + o.y*w1.z + o.z*w2.z + o.w*w3.z;
    float a3 = o.x*w0.w + o.y*w1.w + o.z*w2.w + o.w*w3.w;
    a0 = blockReduceSum128(a0);
    a1 = blockReduceSum128(a1);
    a2 = blockReduceSum128(a2);
    a3 = blockReduceSum128(a3);
    if (threadIdx.x < 4) {
        float a = (threadIdx.x == 0) ? a0 : (threadIdx.x == 1) ? a1 : (threadIdx.x == 2) ? a2 : a3;
        float tp = log1pf(expf(temp[threadIdx.x])) + 0.3f;
        logits[(size_t)row*EH + threadIdx.x] = (a + sal_b[threadIdx.x]) / tp;
    }
}

// ---------------- HMMA causal flash attention: BQ=128, BK=64, HD=64, pre-rope'd fp16 QKV ----------------
#define FPAD 72
#define FSMEM ((128 + 64 + 64)*FPAD*2)   // 36864

__global__ void __launch_bounds__(256, 2) flash_kernel(const __half* __restrict__ QKV,
        __half* __restrict__ Oh) {
    extern __shared__ char fsm[];
    __half* Qh = (__half*)fsm;
    __half* Kh = Qh + 128*FPAD;
    __half* Vt = Kh + 64*FPAD;
    uint32_t uq = smem_to_u32(Qh);
    uint32_t uk = smem_to_u32(Kh);
    uint32_t uv = smem_to_u32(Vt);

    int bh = blockIdx.y;
    int b = bh >> 3, h = bh & 7;
    int q0 = ((int)gridDim.x - 1 - (int)blockIdx.x) * 128;   // heavy tiles first
    int tid = threadIdx.x, lane = tid & 31, wid = tid >> 5;
    int gid = lane >> 2, ctg = lane & 3;
    const int a_row = lane & 15;
    const int a_k   = (lane >> 4) * 8;
    const int b_row = (lane & 7) + ((lane >> 4) << 3);
    const int b_k   = ((lane >> 3) & 1) * 8;
    size_t base = ((size_t)b*TT)*1536 + h*HD;
    const float scl = 0.125f;

    // load Q: plain 16B copies (already rope'd)
    for (int i = tid; i < 128*8; i += 256) {
        int r = i >> 3, c16 = (i & 7) * 8;
        *(uint4*)(Qh + r*FPAD + c16) =
            *(const uint4*)(QKV + base + (size_t)(q0 + r)*1536 + c16);
    }

    float m0 = -1e30f, m1 = -1e30f, l0 = 0.f, l1 = 0.f;
    float oacc[8][4];
    #pragma unroll
    for (int i = 0; i < 8; i++)
        #pragma unroll
        for (int j = 0; j < 4; j++) oacc[i][j] = 0.f;

    int row0 = q0 + wid*16 + gid;
    int nkt = (q0 >> 6) + 2;
    for (int kt = 0; kt < nkt; kt++) {
        int k0 = kt * 64;
        __syncthreads();
        // K: plain copies (already rope'd); V: transpose
        for (int i = tid; i < 64*8; i += 256) {
            int r = i >> 3, c16 = (i & 7) * 8;
            size_t g = base + (size_t)(k0 + r)*1536 + c16;
            *(uint4*)(Kh + r*FPAD + c16) = *(const uint4*)(QKV + g + 512);
        }
        for (int i = tid; i < 64*16; i += 256) {
            int r = i >> 4, dv = (i & 15)*4;
            size_t g = base + (size_t)(k0 + r)*1536 + dv;
            __half2 v0 = ((const __half2*)(QKV + g + 1024))[0];
            __half2 v1 = ((const __half2*)(QKV + g + 1024))[1];
            Vt[(dv+0)*FPAD + r] = __low2half(v0);
            Vt[(dv+1)*FPAD + r] = __high2half(v0);
            Vt[(dv+2)*FPAD + r] = __low2half(v1);
            Vt[(dv+3)*FPAD + r] = __high2half(v1);
        }
        __syncthreads();
        float sacc[8][4];
        #pragma unroll
        for (int nt = 0; nt < 8; nt++)
            #pragma unroll
            for (int j = 0; j < 4; j++) sacc[nt][j] = 0.f;
        #pragma unroll
        for (int kk = 0; kk < 64; kk += 16) {
            uint32_t af[4], bf[4][4];
            LDSM4(af, uq + (uint32_t)((wid*16 + a_row)*FPAD + kk + a_k)*2);
            #pragma unroll
            for (int np = 0; np < 4; np++)
                LDSM4(bf[np], uk + (uint32_t)((np*16 + b_row)*FPAD + kk + b_k)*2);
            #pragma unroll
            for (int np = 0; np < 4; np++) {
                HMMA(sacc[2*np],   af, bf[np][0], bf[np][1]);
                HMMA(sacc[2*np+1], af, bf[np][2], bf[np][3]);
            }
        }
        if (kt >= nkt - 2) {
            #pragma unroll
            for (int nt = 0; nt < 8; nt++) {
                int col = k0 + nt*8 + ctg*2;
                #pragma unroll
                for (int j = 0; j < 4; j++) {
                    int cc = col + (j & 1);
                    int rr = row0 + ((j >> 1) << 3);
                    sacc[nt][j] = (cc <= rr) ? sacc[nt][j]*scl : -1e9f;
                }
            }
        } else {
            #pragma unroll
            for (int nt = 0; nt < 8; nt++)
                #pragma unroll
                for (int j = 0; j < 4; j++) sacc[nt][j] *= scl;
        }
        float rm0 = -1e30f, rm1 = -1e30f;
        #pragma unroll
        for (int nt = 0; nt < 8; nt++) {
            rm0 = fmaxf(rm0, fmaxf(sacc[nt][0], sacc[nt][1]));
            rm1 = fmaxf(rm1, fmaxf(sacc[nt][2], sacc[nt][3]));
        }
        rm0 = fmaxf(rm0, __shfl_xor_sync(0xffffffffu, rm0, 1));
        rm0 = fmaxf(rm0, __shfl_xor_sync(0xffffffffu, rm0, 2));
        rm1 = fmaxf(rm1, __shfl_xor_sync(0xffffffffu, rm1, 1));
        rm1 = fmaxf(rm1, __shfl_xor_sync(0xffffffffu, rm1, 2));
        float mn0 = fmaxf(m0, rm0), mn1 = fmaxf(m1, rm1);
        float c0 = __expf(m0 - mn0), c1 = __expf(m1 - mn1);
        m0 = mn0; m1 = mn1;
        float rs0 = 0.f, rs1 = 0.f;
        #pragma unroll
        for (int nt = 0; nt < 8; nt++) {
            sacc[nt][0] = __expf(sacc[nt][0] - mn0); rs0 += sacc[nt][0];
            sacc[nt][1] = __expf(sacc[nt][1] - mn0); rs0 += sacc[nt][1];
            sacc[nt][2] = __expf(sacc[nt][2] - mn1); rs1 += sacc[nt][2];
            sacc[nt][3] = __expf(sacc[nt][3] - mn1); rs1 += sacc[nt][3];
        }
        rs0 += __shfl_xor_sync(0xffffffffu, rs0, 1);
        rs0 += __shfl_xor_sync(0xffffffffu, rs0, 2);
        rs1 += __shfl_xor_sync(0xffffffffu, rs1, 1);
        rs1 += __shfl_xor_sync(0xffffffffu, rs1, 2);
        l0 = l0*c0 + rs0;
        l1 = l1*c1 + rs1;
        #pragma unroll
        for (int nh = 0; nh < 8; nh++) {
            oacc[nh][0] *= c0; oacc[nh][1] *= c0;
            oacc[nh][2] *= c1; oacc[nh][3] *= c1;
        }
        #pragma unroll
        for (int g = 0; g < 4; g++) {
            uint32_t pf[4];
            pf[0] = f22u(sacc[2*g][0],   sacc[2*g][1]);
            pf[1] = f22u(sacc[2*g][2],   sacc[2*g][3]);
            pf[2] = f22u(sacc[2*g+1][0], sacc[2*g+1][1]);
            pf[3] = f22u(sacc[2*g+1][2], sacc[2*g+1][3]);
            int kof = g*16;
            #pragma unroll
            for (int nh = 0; nh < 4; nh++) {
                uint32_t bf2[4];
                LDSM4(bf2, uv + (uint32_t)((nh*16 + b_row)*FPAD + kof + b_k)*2);
                HMMA(oacc[2*nh],   pf, bf2[0], bf2[1]);
                HMMA(oacc[2*nh+1], pf, bf2[2], bf2[3]);
            }
        }
    }
    float inv0 = 1.f / l0, inv1 = 1.f / l1;
    #pragma unroll
    for (int nh = 0; nh < 8; nh++) {
        int c = nh*8 + ctg*2;
        size_t r0 = (size_t)(b*TT + row0)*DD + h*HD + c;
        size_t r1 = (size_t)(b*TT + row0 + 8)*DD + h*HD + c;
        *(__half2*)(Oh + r0) = __floats2half2_rn(oacc[nh][0]*inv0, oacc[nh][1]*inv0);
        *(__half2*)(Oh + r1) = __floats2half2_rn(oacc[nh][2]*inv1, oacc[nh][3]*inv1);
    }
}

// ---------------- masked softmax pool (512 threads) ----------------
__global__ void __launch_bounds__(512) pool_kernel(
        const int* __restrict__ tokens, const float* __restrict__ logits,
        const float* __restrict__ X, const float* __restrict__ gate_W,
        const float* __restrict__ gate_b,
        float* __restrict__ wv_out, float* __restrict__ u_out) {
    int b = blockIdx.x >> 2, e = blockIdx.x & 3;
    int tid = threadIdx.x;
    __shared__ float ws[TT];
    __shared__ float part[4][EHD];
    int t = tid;
    int mv = (tokens[b*TT + t] != 0);
    float lgv = logits[((size_t)b*TT + t)*EH + e];
    float sf = mv ? lgv : -1e9f;
    float mx = blockReduceMax512(sf);
    float ev = mv ? expf(sf - mx) : 0.f;
    ws[t] = ev;
    float ssum = blockReduceSum512(ev);
    float nvalid = blockReduceSum512((float)mv);
    float wsc = 1.f / (ssum + 1e-6f);
    int tc = tid >> 7, d = tid & 127;
    float acc = 0.f;
    const float* xb = X + ((size_t)b*TT + tc*128)*DD + e*EHD + d;
    #pragma unroll 4
    for (int tt = 0; tt < 128; tt++)
        acc += ws[tc*128 + tt] * xb[(size_t)tt*DD];
    part[tc][d] = acc;
    __syncthreads();
    if (tc == 0) {
        float a = (part[0][d] + part[1][d] + part[2][d] + part[3][d]) * wsc;
        wv_out[b*DD + e*EHD + d] = a;
        part[0][d] = a * gate_W[d];
    }
    __syncthreads();
    if (tid < 32) {
        float g = part[0][tid] + part[0][tid+32] + part[0][tid+64] + part[0][tid+96];
        g = warpReduceSum(g);
        if (tid == 0) {
            float gl = g + gate_b[0];
            u_out[b*EH + e] = (nvalid > 0.f) ? 1.f/(1.f+expf(-gl)) : 0.f;
        }
    }
}

// ---------------- fast/slow state update ----------------
__global__ void update_kernel(const float* __restrict__ wv, const float* __restrict__ u,
                              const float* __restrict__ sal_rms,
                              const float* __restrict__ fast, const float* __restrict__ slow,
                              float* __restrict__ out_fast, float* __restrict__ out_slow) {
    int b = blockIdx.x, tid = threadIdx.x;
    float4 v = ((const float4*)(wv + b*DD))[tid];
    float ss = blockReduceSum128(v.x*v.x + v.y*v.y + v.z*v.z + v.w*v.w);
    float inv = rsqrtf(ss * (1.f/DD) + 1e-6f);
    float4 sr = ((const float4*)sal_rms)[tid];
    int e = tid >> 5;
    float uu = u[b*EH + e];
    float4 f = ((const float4*)(fast + b*DD))[tid];
    float4 s = ((const float4*)(slow + b*DD))[tid];
    float4 wn;
    wn.x = v.x*inv*sr.x; wn.y = v.y*inv*sr.y; wn.z = v.z*inv*sr.z; wn.w = v.w*inv*sr.w;
    float4 nf, ns;
    nf.x = (1.f-uu)*f.x + uu*wn.x;  nf.y = (1.f-uu)*f.y + uu*wn.y;
    nf.z = (1.f-uu)*f.z + uu*wn.z;  nf.w = (1.f-uu)*f.w + uu*wn.w;
    float ud = 0.1f*uu;
    ns.x = (1.f-ud)*s.x + ud*wn.x;  ns.y = (1.f-ud)*s.y + ud*wn.y;
    ns.z = (1.f-ud)*s.z + ud*wn.z;  ns.w = (1.f-ud)*s.w + ud*wn.w;
    ((float4*)(out_fast + b*DD))[tid] = nf;
    ((float4*)(out_slow + b*DD))[tid] = ns;
}

// ---------------- launch ----------------
extern "C" void kernel_launch(void* const* d_in, const int* in_sizes, int n_in,
                              void* d_out, int out_size) {
    const int*   tokens = (const int*)  d_in[0];
    const int*   prev   = (const int*)  d_in[1];
    const float* fast   = (const float*)d_in[2];
    const float* slow   = (const float*)d_in[3];
    const float* embed  = (const float*)d_in[4];
    const float* ctx_W  = (const float*)d_in[5];
    const float* ctx_b  = (const float*)d_in[6];
    const float* etab   = (const float*)d_in[7];
    const float* egate  = (const float*)d_in[8];
    const float* ln1    = (const float*)d_in[9];
    const float* Wq     = (const float*)d_in[10];
    const float* bq     = (const float*)d_in[11];
    const float* Wk     = (const float*)d_in[12];
    const float* bk     = (const float*)d_in[13];
    const float* Wv     = (const float*)d_in[14];
    const float* bv     = (const float*)d_in[15];
    const float* Wo     = (const float*)d_in[16];
    const float* bo     = (const float*)d_in[17];
    const float* ln2    = (const float*)d_in[18];
    const float* W1     = (const float*)d_in[19];
    const float* W2     = (const float*)d_in[20];
    const float* ln_f   = (const float*)d_in[21];
    const float* sal_W  = (const float*)d_in[22];
    const float* sal_b  = (const float*)d_in[23];
    const float* temp   = (const float*)d_in[24];
    const float* gate_W = (const float*)d_in[25];
    const float* gate_b = (const float*)d_in[26];
    const float* sal_rms= (const float*)d_in[27];
    float* out = (float*)d_out;

    float *gx, *gctx, *glog, *gwv, *gu;
    float2 *grope;
    __half *gqkv, *nx, *at, *ff;
    __half *wA, *w1, *w2;
    cudaGetSymbolAddress((void**)&gx,    g_x);
    cudaGetSymbolAddress((void**)&gqkv,  g_qkv);
    cudaGetSymbolAddress((void**)&gctx,  g_ctx);
    cudaGetSymbolAddress((void**)&glog,  g_logits);
    cudaGetSymbolAddress((void**)&gwv,   g_wv);
    cudaGetSymbolAddress((void**)&gu,    g_u);
    cudaGetSymbolAddress((void**)&grope, g_ropetab);
    cudaGetSymbolAddress((void**)&nx,    g_nx);
    cudaGetSymbolAddress((void**)&at,    g_at);
    cudaGetSymbolAddress((void**)&ff,    g_ff);
    cudaGetSymbolAddress((void**)&wA,    g_wqkvo);
    cudaGetSymbolAddress((void**)&w1,    g_w1);
    cudaGetSymbolAddress((void**)&w2,    g_w2);

    cudaFuncSetAttribute(hgemm<0>, cudaFuncAttributeMaxDynamicSharedMemorySize, HSMEM);
    cudaFuncSetAttribute(hgemm<1>, cudaFuncAttributeMaxDynamicSharedMemorySize, HSMEM);
    cudaFuncSetAttribute(hgemm<4>, cudaFuncAttributeMaxDynamicSharedMemorySize, HSMEM);
    cudaFuncSetAttribute(hgemm_ffn, cudaFuncAttributeMaxDynamicSharedMemorySize, HSMEM);
    cudaFuncSetAttribute(flash_kernel, cudaFuncAttributeMaxDynamicSharedMemorySize, FSMEM);

    dim3 tb(32, 8);
    dim3 gD(NTOK/128, DD/128);
    dim3 gQKV(NTOK/128, (3*DD)/128);
    dim3 gFF(NTOK/128, FF/64);

    rope_table_kernel<<<TT, 32>>>(grope);                                                // 1
    tsplit4_kernel<<<dim3(DD/32, DD/32, 4*LL), tb>>>(Wq, Wk, Wv, Wo, wA);                // 2
    ctx_kernel<<<dim3(BB, DD/64), 512>>>(fast, slow, ctx_W, ctx_b, gctx);                // 3
    embed_fused_kernel<<<NTOK, 128>>>(tokens, prev, embed, gctx, etab, egate, ln1,
                                      gx, nx);                                           // 4

    for (int l = 0; l < LL; l++) {
        size_t wo  = (size_t)l*4*DD*DD;
        size_t w1o = (size_t)l*2*FF*DD;
        size_t w2o = (size_t)l*DD*FF;
        if (l > 0)
            rmsnorm_half_kernel<<<NTOK/4, 512>>>(gx, ln1 + l*DD, nx);
        hgemm<0><<<gQKV, 256, HSMEM>>>(nx, wA + wo,
                                       bq + l*DD, bk + l*DD, bv + l*DD,
                                       nullptr, grope, nullptr, gqkv, NTOK, 3*DD, DD);
        if (l == 0) {
            tsplitW1_kernel<<<dim3(FF/32, DD/32, 2*LL), tb>>>(W1, w1);
            tsplit_kernel<<<dim3(DD/32, FF/32, LL), tb>>>(W2, DD, (size_t)FF*DD, w2, (size_t)DD*FF, FF);
        }
        flash_kernel<<<dim3(TT/128, BB*HH), 256, FSMEM>>>(gqkv, at);
        hgemm<1><<<gD, 256, HSMEM>>>(at, wA + wo + (size_t)1536*DD,
                                     bo + l*DD, nullptr, nullptr, gx, nullptr,
                                     gx, nullptr, NTOK, DD, DD);
        rmsnorm_half_kernel<<<NTOK/4, 512>>>(gx, ln2 + l*DD, nx);
        hgemm_ffn<<<gFF, 256, HSMEM>>>(nx, w1 + w1o, w1 + w1o + (size_t)FF*DD,
                                       ff, NTOK, FF, DD);
        hgemm<4><<<gD, 256, HSMEM>>>(ff, w2 + w2o,
                                     nullptr, nullptr, nullptr, gx, nullptr,
                                     gx, nullptr, NTOK, DD, FF);
    }
    rmsnorm_logits_kernel<<<NTOK, 128>>>(gx, ln_f, sal_W, sal_b, temp, out, glog);
    pool_kernel<<<BB*EH, 512>>>(tokens, glog, out, gate_W, gate_b, gwv, gu);
    update_kernel<<<BB, 128>>>(gwv, gu, sal_rms, fast, slow,
                               out + (size_t)NTOK*DD,
                               out + (size_t)NTOK*DD + BB*DD);
}